// round 2
// baseline (speedup 1.0000x reference)
#include <cuda_runtime.h>
#include <cuda_bf16.h>
#include <math.h>
#include <stdint.h>

// x: (16, 256, 64, 64, 4) f32. Per (b,c) slab = 4096 float4 = 64 KB.
// Fused persistent kernel: 256 blocks (one per channel), loop over 16 batches.
// Slab lives in SMEM between the pool phase and the scale phase, so x is read
// from DRAM exactly once. Traffic: 256 MB read + 256 MB write = 512 MB.

#define NB 16
#define NC 256
#define SP 4096            // float4 per (b,c) slab
#define THREADS 512
#define V_PER_T (SP / THREADS)   // 8 float4 per thread

__device__ float4 g_pooled[NB * NC];
__device__ int    g_cnt[NB];

__device__ __forceinline__ int ld_acquire_gpu(const int* p) {
    int v;
    asm volatile("ld.acquire.gpu.global.s32 %0, [%1];" : "=r"(v) : "l"(p) : "memory");
    return v;
}

__global__ void reset_kernel() {
    if (threadIdx.x < NB) g_cnt[threadIdx.x] = 0;
}

__global__ void __launch_bounds__(THREADS, 2)
fused_kernel(const float* __restrict__ x,
             const float* __restrict__ comp_w,
             const float* __restrict__ comp_b,
             const float* __restrict__ exc_w,
             const float* __restrict__ exc_b,
             float* __restrict__ out) {
    extern __shared__ float4 slab[];   // 4096 float4 = 64 KB
    __shared__ float4 red[THREADS / 32];
    __shared__ float4 u_bcast;

    const int c    = blockIdx.x;          // channel 0..255
    const int t    = threadIdx.x;
    const int lane = t & 31;
    const int warp = t >> 5;

    for (int b = 0; b < NB; b++) {
        const size_t base = (size_t)(b * NC + c) * SP;
        const float4* xp = reinterpret_cast<const float4*>(x) + base;

        // ---- Phase 1: load slab -> SMEM, compute per-component max ----
        float4 v[V_PER_T];
        #pragma unroll
        for (int j = 0; j < V_PER_T; j++) v[j] = xp[t + j * THREADS];
        #pragma unroll
        for (int j = 0; j < V_PER_T; j++) slab[t + j * THREADS] = v[j];

        float4 m = v[0];
        #pragma unroll
        for (int j = 1; j < V_PER_T; j++) {
            m.x = fmaxf(m.x, v[j].x);
            m.y = fmaxf(m.y, v[j].y);
            m.z = fmaxf(m.z, v[j].z);
            m.w = fmaxf(m.w, v[j].w);
        }
        #pragma unroll
        for (int o = 16; o > 0; o >>= 1) {
            m.x = fmaxf(m.x, __shfl_xor_sync(0xffffffffu, m.x, o));
            m.y = fmaxf(m.y, __shfl_xor_sync(0xffffffffu, m.y, o));
            m.z = fmaxf(m.z, __shfl_xor_sync(0xffffffffu, m.z, o));
            m.w = fmaxf(m.w, __shfl_xor_sync(0xffffffffu, m.w, o));
        }
        if (lane == 0) red[warp] = m;
        __syncthreads();

        // ---- Publish pooled max, arrive at per-batch barrier ----
        if (t == 0) {
            float4 r = red[0];
            #pragma unroll
            for (int w = 1; w < THREADS / 32; w++) {
                r.x = fmaxf(r.x, red[w].x);
                r.y = fmaxf(r.y, red[w].y);
                r.z = fmaxf(r.z, red[w].z);
                r.w = fmaxf(r.w, red[w].w);
            }
            g_pooled[b * NC + c] = r;
            __threadfence();                       // release pooled write
            atomicAdd(&g_cnt[b], 1);
            while (ld_acquire_gpu(&g_cnt[b]) < NC) __nanosleep(64);
        }
        __syncthreads();   // all threads now see barrier passed

        // ---- Squeeze: dot(pooled[b,:], comp_w) over 256 channels ----
        float s0 = 0.f, s1 = 0.f, s2 = 0.f, s3 = 0.f;
        if (t < NC) {
            float4 p = __ldcg(&g_pooled[b * NC + t]);   // bypass L1 (cross-SM data)
            s0 = p.x * comp_w[0 * NC + t];
            s1 = p.y * comp_w[1 * NC + t];
            s2 = p.z * comp_w[2 * NC + t];
            s3 = p.w * comp_w[3 * NC + t];
        }
        #pragma unroll
        for (int o = 16; o > 0; o >>= 1) {
            s0 += __shfl_xor_sync(0xffffffffu, s0, o);
            s1 += __shfl_xor_sync(0xffffffffu, s1, o);
            s2 += __shfl_xor_sync(0xffffffffu, s2, o);
            s3 += __shfl_xor_sync(0xffffffffu, s3, o);
        }
        if (lane == 0) red[warp] = make_float4(s0, s1, s2, s3);
        __syncthreads();

        if (t == 0) {
            float r  = comp_b[0];
            float xc = comp_b[1];
            float yc = comp_b[2];
            float zc = comp_b[3];
            #pragma unroll
            for (int w = 0; w < NC / 32; w++) {    // only first 8 warps carried data
                r  += red[w].x;
                xc += red[w].y;
                yc += red[w].z;
                zc += red[w].w;
            }
            float u1r = r + xc + yc + zc;
            float u1x = xc - r - zc + yc;
            float u1y = yc + zc - r - xc;
            float u1z = zc - yc + xc - r;
            // excite for this block's channel c
            float r2 = u1r * exc_w[0 * NC + c] + exc_b[0 * NC + c];
            float x2 = u1x * exc_w[1 * NC + c] + exc_b[1 * NC + c];
            float y2 = u1y * exc_w[2 * NC + c] + exc_b[2 * NC + c];
            float z2 = u1z * exc_w[3 * NC + c] + exc_b[3 * NC + c];
            u_bcast = make_float4(r2 + x2 + y2 + z2,
                                  x2 - r2 - z2 + y2,
                                  y2 + z2 - r2 - x2,
                                  z2 - y2 + x2 - r2);
        }
        __syncthreads();
        float4 u = u_bcast;

        // ---- Phase 2: scale slab from SMEM, write out (no x re-read) ----
        float4* op = reinterpret_cast<float4*>(out) + base;
        #pragma unroll
        for (int j = 0; j < V_PER_T; j++) {
            float4 s = slab[t + j * THREADS];
            op[t + j * THREADS] = make_float4(s.x * u.x, s.y * u.y, s.z * u.z, s.w * u.w);
        }
        __syncthreads();   // protect slab before next batch overwrites it
    }
}

extern "C" void kernel_launch(void* const* d_in, const int* in_sizes, int n_in,
                              void* d_out, int out_size) {
    const float* x      = (const float*)d_in[0];
    const float* comp_w = (const float*)d_in[1];
    const float* comp_b = (const float*)d_in[2];
    const float* exc_w  = (const float*)d_in[3];
    const float* exc_b  = (const float*)d_in[4];
    float* out = (float*)d_out;

    static bool attr_set = false;
    if (!attr_set) {
        cudaFuncSetAttribute(fused_kernel,
                             cudaFuncAttributeMaxDynamicSharedMemorySize,
                             SP * sizeof(float4));
        attr_set = true;
    }

    reset_kernel<<<1, 32>>>();
    fused_kernel<<<NC, THREADS, SP * sizeof(float4)>>>(x, comp_w, comp_b,
                                                       exc_w, exc_b, out);
}